// round 16
// baseline (speedup 1.0000x reference)
#include <cuda_runtime.h>
#include <cuda_bf16.h>
#include <cstdint>

// ---------------------------------------------------------------------------
// Nystrom attention transformer layer. TF32 mma GEMMs, 64x64 warp tiles,
// 3-stage single-sync cp.async pipelines, conflict-free smem, fused epilogues.
// Three-stream graph: TWO parallel pinv chains overlap sim1/flash(sim3*v)/conv.
// ---------------------------------------------------------------------------

#define B_    4
#define N_    4096
#define DIM_  512
#define H_    8
#define DH_   64
#define M_    256
#define L_    16
#define ROWS_ (B_ * N_)          // 16384
#define BH_   (B_ * H_)          // 32

// ---------------- scratch (device globals) ----------------------------------
__device__ float g_ln  [ROWS_ * DIM_];
__device__ float g_q   [BH_ * N_ * DH_];
__device__ float g_k   [BH_ * N_ * DH_];
__device__ float g_v   [BH_ * N_ * DH_];
__device__ float g_ql  [BH_ * M_ * DH_];
__device__ float g_kl  [BH_ * M_ * DH_];
__device__ float g_a1  [BH_ * N_ * M_];
__device__ float g_a2  [BH_ * M_ * M_];
__device__ float g_z0  [BH_ * M_ * M_];
__device__ float g_z1  [BH_ * M_ * M_];
__device__ float g_t1  [BH_ * M_ * M_];
__device__ float g_t2  [BH_ * M_ * M_];
__device__ float g_t3  [BH_ * M_ * M_];
__device__ float g_a3v [BH_ * M_ * DH_];
__device__ float g_w   [BH_ * M_ * DH_];    // a2inv @ a3v
__device__ float g_part[BH_ * 4 * M_ * DH_];
__device__ float g_rsum[BH_ * M_];
__device__ float g_ctx [ROWS_ * DIM_];
__device__ float g_max [2];

// ---------------- reductions -------------------------------------------------
__device__ __forceinline__ float blockReduceMax(float v, float* sh) {
    int tid = threadIdx.x;
    sh[tid] = v; __syncthreads();
    for (int s = 128; s > 0; s >>= 1) {
        if (tid < s) sh[tid] = fmaxf(sh[tid], sh[tid + s]);
        __syncthreads();
    }
    float r = sh[0]; __syncthreads();
    return r;
}

// ---------------- layernorm: warp per row, single pass ------------------------
__global__ __launch_bounds__(256) void ln_kernel(
    const float* __restrict__ x, const float* __restrict__ w,
    const float* __restrict__ b)
{
    int tid = threadIdx.x;
    if (blockIdx.x < 32) {
        g_rsum[blockIdx.x * 256 + tid] = 0.f;
        if (blockIdx.x == 0 && tid < 2) g_max[tid] = 0.f;
    }

    long long row = (long long)blockIdx.x * 8 + (tid >> 5);
    int lane = tid & 31;
    const float* xr = x + row * DIM_;

    float4 v[4];
    float s = 0.f, s2 = 0.f;
    #pragma unroll
    for (int i = 0; i < 4; i++) {
        v[i] = *(const float4*)(xr + (i * 32 + lane) * 4);
        s  += v[i].x + v[i].y + v[i].z + v[i].w;
        s2 += v[i].x * v[i].x + v[i].y * v[i].y
            + v[i].z * v[i].z + v[i].w * v[i].w;
    }
    #pragma unroll
    for (int d = 16; d > 0; d >>= 1) {
        s  += __shfl_xor_sync(0xffffffffu, s, d);
        s2 += __shfl_xor_sync(0xffffffffu, s2, d);
    }
    float mu  = s * (1.0f / DIM_);
    float var = s2 * (1.0f / DIM_) - mu * mu;
    float inv = rsqrtf(var + 1e-5f);

    float* dst = g_ln + row * DIM_;
    #pragma unroll
    for (int i = 0; i < 4; i++) {
        int col = (i * 32 + lane) * 4;
        float4 wv = *(const float4*)(w + col);
        float4 bv = *(const float4*)(b + col);
        float4 o;
        o.x = (v[i].x - mu) * inv * wv.x + bv.x;
        o.y = (v[i].y - mu) * inv * wv.y + bv.y;
        o.z = (v[i].z - mu) * inv * wv.z + bv.z;
        o.w = (v[i].w - mu) * inv * wv.w + bv.w;
        *(float4*)(dst + col) = o;
    }
}

// ---------------- mma + cp.async helpers -------------------------------------
__device__ __forceinline__ void mma_tf32(
    float& c0, float& c1, float& c2, float& c3,
    uint32_t a0, uint32_t a1, uint32_t a2, uint32_t a3,
    uint32_t b0, uint32_t b1)
{
    asm volatile(
        "mma.sync.aligned.m16n8k8.row.col.f32.tf32.tf32.f32 "
        "{%0,%1,%2,%3}, {%4,%5,%6,%7}, {%8,%9}, {%0,%1,%2,%3};"
        : "+f"(c0), "+f"(c1), "+f"(c2), "+f"(c3)
        : "r"(a0), "r"(a1), "r"(a2), "r"(a3), "r"(b0), "r"(b1));
}
__device__ __forceinline__ void cpa16(void* dst, const void* src) {
    uint32_t d = (uint32_t)__cvta_generic_to_shared(dst);
    asm volatile("cp.async.cg.shared.global [%0], [%1], 16;" :: "r"(d), "l"(src));
}
#define CP_COMMIT() asm volatile("cp.async.commit_group;" ::: "memory")
#define CP_WAIT1()  asm volatile("cp.async.wait_group 1;" ::: "memory")
#define CP_WAIT0()  asm volatile("cp.async.wait_group 0;" ::: "memory")

#define BK2 16
#define RS  20      // [row][k] stride (words): frag banks 20g+tg = all 32 distinct

// ---------------- main mma GEMM: 128 threads, 2x2 warps, 64x64 warp tile -----
// 3-stage single-sync pipeline for ALL tile shapes.
// MODE 0: standard epilogue; MODE 1: qkv split; MODE 2: ctx accumulate.
template<int BM, int BN, bool TB, int MODE, bool SPLITK>
__global__ __launch_bounds__(128, (BN == 64) ? 3 : 2) void mma_gemm_kernel(
    const float* __restrict__ A, const float* __restrict__ B,
    float* __restrict__ C, int Ndim, int Kdim, int ldA, int ldB,
    long long sA, long long sB, long long sC,
    float alpha,
    const float* __restrict__ resid, float residScale,
    const float* __restrict__ residScalePtr,
    const float* __restrict__ bias)
{
    constexpr int MT = 4;
    constexpr int NT = BN / 16;
    constexpr int RSB = BN + 8;
    constexpr int ASZ = BM * RS;
    constexpr int BSZ = TB ? BN * RS : BK2 * RSB;
    constexpr int STG = ASZ + BSZ;

    extern __shared__ __align__(16) float smp[];   // 3 stages

    int bz = blockIdx.z;
    long long aOff, bOff, cOff;
    if (SPLITK) {
        int bz0 = bz >> 2, sp = bz & 3;
        aOff = (long long)bz0 * sA + (long long)sp * Kdim;
        bOff = (long long)bz0 * sB + (long long)sp * Kdim * ldB;
        cOff = (long long)bz * sC;
    } else {
        aOff = (long long)bz * sA;
        bOff = (long long)bz * sB;
        cOff = (long long)bz * sC;
    }
    const float* Ab = A + aOff;
    const float* Bb = B + bOff;
    float*       Cb = C + cOff;
    const float* Rb = resid ? resid + cOff : nullptr;

    int n0 = blockIdx.x * BN;
    int m0 = blockIdx.y * BM;
    int tid  = threadIdx.x;
    int wid  = tid >> 5;
    int lane = tid & 31;
    int wm = wid >> 1, wn = wid & 1;
    int tm0 = wm * 64, tn0 = wn * (BN / 2);
    int g  = lane >> 2;
    int tg = lane & 3;

    float acc[MT][NT][4];
    #pragma unroll
    for (int i = 0; i < MT; i++)
        #pragma unroll
        for (int j = 0; j < NT; j++)
            #pragma unroll
            for (int c = 0; c < 4; c++) acc[i][j][c] = 0.f;

    auto loadTile = [&](int t, int st) {
        int k0 = t * BK2;
        float* As = smp + st * STG;
        float* Bs = As + ASZ;
        #pragma unroll
        for (int c = 0; c < BM / 32; c++) {
            int id = c * 128 + tid;
            int m = id >> 2, kq = (id & 3) * 4;
            cpa16(&As[m * RS + kq],
                  Ab + (long long)(m0 + m) * ldA + k0 + kq);
        }
        if (TB) {
            #pragma unroll
            for (int c = 0; c < BN / 32; c++) {
                int id = c * 128 + tid;
                int n = id >> 2, kq = (id & 3) * 4;
                cpa16(&Bs[n * RS + kq],
                      Bb + (long long)(n0 + n) * ldB + k0 + kq);
            }
        } else {
            constexpr int CPR = BN / 4;
            #pragma unroll
            for (int c = 0; c < BN / 32; c++) {
                int id = c * 128 + tid;
                int k = id / CPR, nq = (id % CPR) * 4;
                cpa16(&Bs[k * RSB + nq],
                      Bb + (long long)(k0 + k) * ldB + n0 + nq);
            }
        }
    };

    auto computeStage = [&](int st) {
        const float* as = smp + st * STG;
        const float* bs = as + ASZ;
        #pragma unroll
        for (int kk = 0; kk < BK2; kk += 8) {
            int c0 = kk + tg, c1 = c0 + 4;
            uint32_t af[MT][4], bf[NT][2];
            #pragma unroll
            for (int i = 0; i < MT; i++) {
                int r0 = (tm0 + i * 16 + g) * RS;
                int r1 = r0 + 8 * RS;
                af[i][0] = __float_as_uint(as[r0 + c0]);
                af[i][1] = __float_as_uint(as[r1 + c0]);
                af[i][2] = __float_as_uint(as[r0 + c1]);
                af[i][3] = __float_as_uint(as[r1 + c1]);
            }
            #pragma unroll
            for (int j = 0; j < NT; j++) {
                if (TB) {
                    int rn = (tn0 + j * 8 + g) * RS;
                    bf[j][0] = __float_as_uint(bs[rn + c0]);
                    bf[j][1] = __float_as_uint(bs[rn + c1]);
                } else {
                    int b0 = c0 * RSB + tn0 + j * 8 + g;
                    bf[j][0] = __float_as_uint(bs[b0]);
                    bf[j][1] = __float_as_uint(bs[b0 + 4 * RSB]);
                }
            }
            #pragma unroll
            for (int i = 0; i < MT; i++)
                #pragma unroll
                for (int j = 0; j < NT; j++)
                    mma_tf32(acc[i][j][0], acc[i][j][1], acc[i][j][2], acc[i][j][3],
                             af[i][0], af[i][1], af[i][2], af[i][3],
                             bf[j][0], bf[j][1]);
        }
    };

    int nIter = Kdim / BK2;
    loadTile(0, 0); CP_COMMIT();
    loadTile(1, 1); CP_COMMIT();
    int p = 0;
    for (int t = 0; t < nIter; t++) {
        CP_WAIT1();
        __syncthreads();
        if (t + 2 < nIter) {
            int st = p + 2; if (st >= 3) st -= 3;
            loadTile(t + 2, st);
        }
        CP_COMMIT();
        computeStage(p);
        p = (p + 1 == 3) ? 0 : p + 1;
    }

    float rs = residScalePtr ? *residScalePtr : residScale;
    #pragma unroll
    for (int i = 0; i < MT; i++) {
        int r0 = m0 + tm0 + i * 16 + g;
        int r1 = r0 + 8;
        #pragma unroll
        for (int j = 0; j < NT; j++) {
            int cc = n0 + tn0 + j * 8 + tg * 2;
            if (MODE == 0) {
                float2 bv = bias ? *(const float2*)(bias + cc) : make_float2(0.f, 0.f);
                float2 v0 = make_float2(alpha * acc[i][j][0] + bv.x,
                                        alpha * acc[i][j][1] + bv.y);
                float2 v1 = make_float2(alpha * acc[i][j][2] + bv.x,
                                        alpha * acc[i][j][3] + bv.y);
                if (Rb) {
                    float2 q0 = *(const float2*)(Rb + (long long)r0 * Ndim + cc);
                    float2 q1 = *(const float2*)(Rb + (long long)r1 * Ndim + cc);
                    v0.x += rs * q0.x; v0.y += rs * q0.y;
                    v1.x += rs * q1.x; v1.y += rs * q1.y;
                }
                *(float2*)(Cb + (long long)r0 * Ndim + cc) = v0;
                *(float2*)(Cb + (long long)r1 * Ndim + cc) = v1;
            } else if (MODE == 1) {
                int which = cc >> 9;
                int hc = cc & 511;
                int h = hc >> 6, d = hc & 63;
                float sc = (which == 0) ? 0.125f : 1.0f;
                float* dstbuf = (which == 0) ? g_q : (which == 1) ? g_k : g_v;
                #pragma unroll
                for (int rr = 0; rr < 2; rr++) {
                    int row = rr ? r1 : r0;
                    int b = row >> 12, nn = row & 4095;
                    long long dst = (((long long)((b << 3) + h)) * N_ + nn) * DH_ + d;
                    float2 v = rr ? make_float2(sc * acc[i][j][2], sc * acc[i][j][3])
                                  : make_float2(sc * acc[i][j][0], sc * acc[i][j][1]);
                    *(float2*)(dstbuf + dst) = v;
                }
            } else {
                // MODE 2: accumulate into ctx (conv residual already written)
                int b = bz >> 3, h = bz & 7;
                float* c0p = g_ctx + ((long long)(b * N_ + r0)) * DIM_ + h * DH_ + cc;
                float* c1p = g_ctx + ((long long)(b * N_ + r1)) * DIM_ + h * DH_ + cc;
                float2 o0 = *(float2*)c0p;
                float2 o1 = *(float2*)c1p;
                *(float2*)c0p = make_float2(o0.x + acc[i][j][0], o0.y + acc[i][j][1]);
                *(float2*)c1p = make_float2(o1.x + acc[i][j][2], o1.y + acc[i][j][3]);
            }
        }
    }
}

// ---------------- flash sim3*v: a3v partials without materializing exp(sim3) --
#define FL_QL 0                       // 128 x 68
#define FL_KS 8704                    // 2 x (64 x 68)
#define FL_VS 17408                   // 2 x (64 x 72)
#define FL_SS 26624                   // 128 x 68
#define FL_SMEM ((26624 + 8704) * 4)  // 141312 B

__global__ __launch_bounds__(256, 1) void a3v_flash_kernel()
{
    extern __shared__ __align__(16) float fsm[];
    float* QL  = fsm + FL_QL;
    float* KS0 = fsm + FL_KS;
    float* VS0 = fsm + FL_VS;
    float* SS  = fsm + FL_SS;

    int ns = blockIdx.x;
    int mb = blockIdx.y;
    int bh = blockIdx.z;
    int m0 = mb * 128;
    const float* qlb = g_ql + (long long)bh * (M_ * DH_);
    const float* kb  = g_k + (long long)bh * (N_ * DH_) + (long long)ns * 2048 * DH_;
    const float* vb  = g_v + (long long)bh * (N_ * DH_) + (long long)ns * 2048 * DH_;

    int tid = threadIdx.x;
    int wid = tid >> 5, lane = tid & 31;
    int wm = wid >> 1, wn = wid & 1;
    int tm0 = wm * 32, tn0 = wn * 32;
    int g = lane >> 2, tg = lane & 3;

    auto loadKV = [&](int t, int st) {
        const float* kb2 = kb + (long long)t * 64 * DH_;
        const float* vb2 = vb + (long long)t * 64 * DH_;
        float* KS = KS0 + st * 4352;
        float* VS = VS0 + st * 4608;
        #pragma unroll
        for (int c = 0; c < 4; c++) {
            int id = c * 256 + tid;
            int n = id >> 4, kq = (id & 15) * 4;
            cpa16(&KS[n * 68 + kq], kb2 + (long long)n * DH_ + kq);
        }
        #pragma unroll
        for (int c = 0; c < 4; c++) {
            int id = c * 256 + tid;
            int k = id >> 4, nq = (id & 15) * 4;
            cpa16(&VS[k * 72 + nq], vb2 + (long long)k * DH_ + nq);
        }
    };

    #pragma unroll
    for (int c = 0; c < 8; c++) {
        int id = c * 256 + tid;
        int m = id >> 4, kq = (id & 15) * 4;
        cpa16(&QL[m * 68 + kq], qlb + (long long)(m0 + m) * DH_ + kq);
    }
    loadKV(0, 0);
    CP_COMMIT();

    float acc_o[2][4][4];
    #pragma unroll
    for (int i = 0; i < 2; i++)
        #pragma unroll
        for (int j = 0; j < 4; j++)
            #pragma unroll
            for (int c = 0; c < 4; c++) acc_o[i][j][c] = 0.f;
    float rsp[2][2] = {{0.f, 0.f}, {0.f, 0.f}};

    int p = 0;
    for (int t = 0; t < 32; t++) {
        if (t + 1 < 32) loadKV(t + 1, 1 - p);
        CP_COMMIT();
        CP_WAIT1();
        __syncthreads();

        const float* KS = KS0 + p * 4352;
        const float* VS = VS0 + p * 4608;

        float acc_s[2][4][4];
        #pragma unroll
        for (int i = 0; i < 2; i++)
            #pragma unroll
            for (int j = 0; j < 4; j++)
                #pragma unroll
                for (int c = 0; c < 4; c++) acc_s[i][j][c] = 0.f;

        #pragma unroll
        for (int kk = 0; kk < 64; kk += 8) {
            int c0 = kk + tg, c1 = c0 + 4;
            uint32_t af[2][4], bf[4][2];
            #pragma unroll
            for (int i = 0; i < 2; i++) {
                int r0 = (tm0 + i * 16 + g) * 68;
                int r1 = r0 + 8 * 68;
                af[i][0] = __float_as_uint(QL[r0 + c0]);
                af[i][1] = __float_as_uint(QL[r1 + c0]);
                af[i][2] = __float_as_uint(QL[r0 + c1]);
                af[i][3] = __float_as_uint(QL[r1 + c1]);
            }
            #pragma unroll
            for (int j = 0; j < 4; j++) {
                int rn = (tn0 + j * 8 + g) * 68;
                bf[j][0] = __float_as_uint(KS[rn + c0]);
                bf[j][1] = __float_as_uint(KS[rn + c1]);
            }
            #pragma unroll
            for (int i = 0; i < 2; i++)
                #pragma unroll
                for (int j = 0; j < 4; j++)
                    mma_tf32(acc_s[i][j][0], acc_s[i][j][1], acc_s[i][j][2], acc_s[i][j][3],
                             af[i][0], af[i][1], af[i][2], af[i][3],
                             bf[j][0], bf[j][1]);
        }

        #pragma unroll
        for (int i = 0; i < 2; i++) {
            int r0 = tm0 + i * 16 + g;
            int r1 = r0 + 8;
            #pragma unroll
            for (int j = 0; j < 4; j++) {
                int col = tn0 + j * 8 + tg * 2;
                float e0 = __expf(acc_s[i][j][0]);
                float e1 = __expf(acc_s[i][j][1]);
                float e2 = __expf(acc_s[i][j][2]);
                float e3 = __expf(acc_s[i][j][3]);
                rsp[i][0] += e0 + e1;
                rsp[i][1] += e2 + e3;
                *(float2*)(SS + r0 * 68 + col) = make_float2(e0, e1);
                *(float2*)(SS + r1 * 68 + col) = make_float2(e2, e3);
            }
        }
        __syncthreads();

        #pragma unroll
        for (int kk = 0; kk < 64; kk += 8) {
            int c0 = kk + tg, c1 = c0 + 4;
            uint32_t af[2][4], bf[4][2];
            #pragma unroll
            for (int i = 0; i < 2; i++) {
                int r0 = (tm0 + i * 16 + g) * 68;
                int r1 = r0 + 8 * 68;
                af[i][0] = __float_as_uint(SS[r0 + c0]);
                af[i][1] = __float_as_uint(SS[r1 + c0]);
                af[i][2] = __float_as_uint(SS[r0 + c1]);
                af[i][3] = __float_as_uint(SS[r1 + c1]);
            }
            #pragma unroll
            for (int j = 0; j < 4; j++) {
                int b0 = c0 * 72 + tn0 + j * 8 + g;
                bf[j][0] = __float_as_uint(VS[b0]);
                bf[j][1] = __float_as_uint(VS[b0 + 4 * 72]);
            }
            #pragma unroll
            for (int i = 0; i < 2; i++)
                #pragma unroll
                for (int j = 0; j < 4; j++)
                    mma_tf32(acc_o[i][j][0], acc_o[i][j][1], acc_o[i][j][2], acc_o[i][j][3],
                             af[i][0], af[i][1], af[i][2], af[i][3],
                             bf[j][0], bf[j][1]);
        }
        __syncthreads();
        p ^= 1;
    }

    long long pbase = ((long long)bh * 4 + ns) * (M_ * DH_);
    #pragma unroll
    for (int i = 0; i < 2; i++) {
        int r0 = tm0 + i * 16 + g;
        int r1 = r0 + 8;
        #pragma unroll
        for (int j = 0; j < 4; j++) {
            int col = tn0 + j * 8 + tg * 2;
            *(float2*)(g_part + pbase + (long long)(m0 + r0) * DH_ + col) =
                make_float2(acc_o[i][j][0], acc_o[i][j][1]);
            *(float2*)(g_part + pbase + (long long)(m0 + r1) * DH_ + col) =
                make_float2(acc_o[i][j][2], acc_o[i][j][3]);
        }
        float s0 = rsp[i][0], s1 = rsp[i][1];
        s0 += __shfl_xor_sync(0xffffffffu, s0, 1);
        s0 += __shfl_xor_sync(0xffffffffu, s0, 2);
        s1 += __shfl_xor_sync(0xffffffffu, s1, 1);
        s1 += __shfl_xor_sync(0xffffffffu, s1, 2);
        if (tg == 0) {
            atomicAdd(&g_rsum[bh * M_ + m0 + r0], s0);
            atomicAdd(&g_rsum[bh * M_ + m0 + r1], s1);
        }
    }
}

// ---------------- sim GEMM (TB) with fused full-row softmax ------------------
__global__ __launch_bounds__(256) void sim_softmax_kernel(
    const float* __restrict__ A, const float* __restrict__ Bm,
    float* __restrict__ C, int Kdim,
    long long sA, long long sB, long long sC)
{
    constexpr int BMs = 64;
    __shared__ __align__(16) float As[BMs * RS];
    __shared__ __align__(16) float Bs[256 * RS];
    __shared__ float redM[4][BMs];
    __shared__ float redS[4][BMs];

    int bz = blockIdx.z;
    const float* Ab = A + (long long)bz * sA;
    const float* Bb = Bm + (long long)bz * sB;
    float*       Cb = C + (long long)bz * sC;

    int m0 = blockIdx.y * BMs;
    int tid  = threadIdx.x;
    int wid  = tid >> 5;
    int lane = tid & 31;
    int wm = wid >> 2, wn = wid & 3;
    int tm0 = wm * 32, tn0 = wn * 64;
    int g  = lane >> 2;
    int tg = lane & 3;

    float acc[2][8][4];
    #pragma unroll
    for (int i = 0; i < 2; i++)
        #pragma unroll
        for (int j = 0; j < 8; j++)
            #pragma unroll
            for (int c = 0; c < 4; c++) acc[i][j][c] = 0.f;

    for (int k0 = 0; k0 < Kdim; k0 += BK2) {
        {
            int m = tid >> 2, kq = (tid & 3) * 4;
            cpa16(&As[m * RS + kq], Ab + (long long)(m0 + m) * Kdim + k0 + kq);
        }
        #pragma unroll
        for (int c = 0; c < 4; c++) {
            int id = c * 256 + tid;
            int n = id >> 2, kq = (id & 3) * 4;
            cpa16(&Bs[n * RS + kq], Bb + (long long)n * Kdim + k0 + kq);
        }
        CP_COMMIT();
        CP_WAIT0();
        __syncthreads();

        #pragma unroll
        for (int kk = 0; kk < BK2; kk += 8) {
            int c0 = kk + tg, c1 = c0 + 4;
            uint32_t af[2][4], bf[8][2];
            #pragma unroll
            for (int i = 0; i < 2; i++) {
                int r0 = (tm0 + i * 16 + g) * RS;
                int r1 = r0 + 8 * RS;
                af[i][0] = __float_as_uint(As[r0 + c0]);
                af[i][1] = __float_as_uint(As[r1 + c0]);
                af[i][2] = __float_as_uint(As[r0 + c1]);
                af[i][3] = __float_as_uint(As[r1 + c1]);
            }
            #pragma unroll
            for (int j = 0; j < 8; j++) {
                int rn = (tn0 + j * 8 + g) * RS;
                bf[j][0] = __float_as_uint(Bs[rn + c0]);
                bf[j][1] = __float_as_uint(Bs[rn + c1]);
            }
            #pragma unroll
            for (int i = 0; i < 2; i++)
                #pragma unroll
                for (int j = 0; j < 8; j++)
                    mma_tf32(acc[i][j][0], acc[i][j][1], acc[i][j][2], acc[i][j][3],
                             af[i][0], af[i][1], af[i][2], af[i][3],
                             bf[j][0], bf[j][1]);
        }
        __syncthreads();
    }

    #pragma unroll
    for (int i = 0; i < 2; i++) {
        float mx0 = -1e30f, mx1 = -1e30f;
        #pragma unroll
        for (int j = 0; j < 8; j++) {
            mx0 = fmaxf(mx0, fmaxf(acc[i][j][0], acc[i][j][1]));
            mx1 = fmaxf(mx1, fmaxf(acc[i][j][2], acc[i][j][3]));
        }
        mx0 = fmaxf(mx0, __shfl_xor_sync(0xffffffffu, mx0, 1));
        mx0 = fmaxf(mx0, __shfl_xor_sync(0xffffffffu, mx0, 2));
        mx1 = fmaxf(mx1, __shfl_xor_sync(0xffffffffu, mx1, 1));
        mx1 = fmaxf(mx1, __shfl_xor_sync(0xffffffffu, mx1, 2));
        if (tg == 0) {
            redM[wn][tm0 + i * 16 + g]     = mx0;
            redM[wn][tm0 + i * 16 + g + 8] = mx1;
        }
    }
    __syncthreads();
    #pragma unroll
    for (int i = 0; i < 2; i++) {
        int rb0 = tm0 + i * 16 + g, rb1 = rb0 + 8;
        float mx0 = fmaxf(fmaxf(redM[0][rb0], redM[1][rb0]),
                          fmaxf(redM[2][rb0], redM[3][rb0]));
        float mx1 = fmaxf(fmaxf(redM[0][rb1], redM[1][rb1]),
                          fmaxf(redM[2][rb1], redM[3][rb1]));
        float s0 = 0.f, s1 = 0.f;
        #pragma unroll
        for (int j = 0; j < 8; j++) {
            float e0 = __expf(acc[i][j][0] - mx0);
            float e1 = __expf(acc[i][j][1] - mx0);
            float e2 = __expf(acc[i][j][2] - mx1);
            float e3 = __expf(acc[i][j][3] - mx1);
            acc[i][j][0] = e0; acc[i][j][1] = e1;
            acc[i][j][2] = e2; acc[i][j][3] = e3;
            s0 += e0 + e1; s1 += e2 + e3;
        }
        s0 += __shfl_xor_sync(0xffffffffu, s0, 1);
        s0 += __shfl_xor_sync(0xffffffffu, s0, 2);
        s1 += __shfl_xor_sync(0xffffffffu, s1, 1);
        s1 += __shfl_xor_sync(0xffffffffu, s1, 2);
        if (tg == 0) { redS[wn][rb0] = s0; redS[wn][rb1] = s1; }
    }
    __syncthreads();
    #pragma unroll
    for (int i = 0; i < 2; i++) {
        int rb0 = tm0 + i * 16 + g, rb1 = rb0 + 8;
        float i0 = 1.f / (redS[0][rb0] + redS[1][rb0] + redS[2][rb0] + redS[3][rb0]);
        float i1 = 1.f / (redS[0][rb1] + redS[1][rb1] + redS[2][rb1] + redS[3][rb1]);
        int r0 = m0 + rb0, r1 = m0 + rb1;
        #pragma unroll
        for (int j = 0; j < 8; j++) {
            int cc = tn0 + j * 8 + tg * 2;
            *(float2*)(Cb + (long long)r0 * 256 + cc) =
                make_float2(acc[i][j][0] * i0, acc[i][j][1] * i0);
            *(float2*)(Cb + (long long)r1 * 256 + cc) =
                make_float2(acc[i][j][2] * i1, acc[i][j][3] * i1);
        }
    }
}

// ---------------- landmark means ---------------------------------------------
__global__ __launch_bounds__(256) void landmark_kernel()
{
    int id = blockIdx.x * 256 + threadIdx.x;
    const int half = BH_ * M_ * DH_;
    bool isK = id >= half;
    int t = isK ? id - half : id;
    int d  = t & 63;
    int m  = (t >> 6) & 255;
    int bh = t >> 14;
    const float* src = (isK ? g_k : g_q) + ((long long)bh * N_ + m * L_) * DH_ + d;
    float s = 0.f;
    #pragma unroll
    for (int l = 0; l < L_; l++) s += src[l * DH_];
    (isK ? g_kl : g_ql)[t] = s * (1.0f / L_);
}

// ---------------- a3v 2-split reduce + row normalize -------------------------
__global__ __launch_bounds__(256) void a3v_reduce_kernel()
{
    int idx = blockIdx.x * 256 + threadIdx.x;
    int rrow = idx >> 6;
    int bh = idx >> 14;
    int inner = idx & 16383;
    long long base = (long long)bh * 4 * 16384 + inner;
    float s = g_part[base] + g_part[base + 16384];
    g_a3v[idx] = s / g_rsum[rrow];
}

// ---------------- pinv init ---------------------------------------------------
__global__ __launch_bounds__(256) void pinv_absmax_kernel()
{
    __shared__ float sh[256];
    const float* X = g_a2 + (long long)blockIdx.x * (M_ * M_);
    int tid = threadIdx.x;
    float cs = 0.f, rs = 0.f;
    for (int j = 0; j < M_; j++) cs += fabsf(X[tid * M_ + j]);
    for (int i = 0; i < M_; i++) rs += fabsf(X[i * M_ + tid]);
    float cm = blockReduceMax(cs, sh);
    float rm = blockReduceMax(rs, sh);
    if (tid == 0) {
        atomicMax(reinterpret_cast<int*>(&g_max[0]), __float_as_int(cm));
        atomicMax(reinterpret_cast<int*>(&g_max[1]), __float_as_int(rm));
    }
}

__global__ __launch_bounds__(256) void zinit_kernel()
{
    long long id = (long long)blockIdx.x * 256 + threadIdx.x;
    float inv = 1.0f / (g_max[0] * g_max[1]);
    long long bh = id >> 16;
    int rem = (int)(id & 65535);
    int row = rem >> 8, col = rem & 255;
    g_z0[id] = g_a2[bh * (M_ * M_) + (long long)col * M_ + row] * inv;
}

// ---------------- depthwise conv residual: WRITES ctx (step 9 accumulates) ----
__global__ __launch_bounds__(256) void conv_add_kernel(const float* __restrict__ cw)
{
    __shared__ __align__(16) float sv[160 * 64];

    int bid = blockIdx.x;
    int bh = bid >> 5;
    int tile = bid & 31;
    int n0 = tile * 128;
    int h = bh & 7, b = bh >> 3;
    int tid = threadIdx.x;
    const float* vb = g_v + ((long long)bh << 18);

    #pragma unroll
    for (int c = 0; c < 10; c++) {
        int e = (c * 256 + tid) * 4;
        int r = e >> 6, d = e & 63;
        int gr = n0 - 16 + r;
        float4 val = make_float4(0.f, 0.f, 0.f, 0.f);
        if ((unsigned)gr < (unsigned)N_)
            val = *(const float4*)(vb + (long long)gr * DH_ + d);
        *(float4*)(sv + r * 64 + d) = val;
    }
    __syncthreads();

    int d = tid & 63, rg = tid >> 6;
    float wr[33];
    #pragma unroll
    for (int k = 0; k < 33; k++) wr[k] = cw[h * 33 + k];

    #pragma unroll
    for (int half = 0; half < 2; half++) {
        int ob = rg * 32 + half * 16;
        float in[48];
        #pragma unroll
        for (int j = 0; j < 48; j++) in[j] = sv[(ob + j) * 64 + d];
        #pragma unroll
        for (int i = 0; i < 16; i++) {
            float acc = 0.f;
            #pragma unroll
            for (int k = 0; k < 33; k++) acc += wr[k] * in[i + k];
            int grow = n0 + ob + i;
            g_ctx[((long long)(b * N_ + grow)) * DIM_ + h * DH_ + d] = acc;
        }
    }
}

// ---------------- host helpers -------------------------------------------------
static float* symaddr(const void* sym) {
    void* p = nullptr;
    cudaGetSymbolAddress(&p, sym);
    return (float*)p;
}

template<int BM, int BN, bool TB, int MODE, bool SPLITK>
static void launch_gemm(dim3 grid,
                 const float* A, const float* B, float* C,
                 int N, int K, int ldA, int ldB,
                 long long sA, long long sB, long long sC,
                 float alpha, const float* resid, float rs,
                 const float* rsPtr, const float* bias,
                 cudaStream_t st = 0)
{
    constexpr int RSB = BN + 8;
    constexpr int ASZ = BM * RS;
    constexpr int BSZ = TB ? BN * RS : BK2 * RSB;
    int smem = 3 * (ASZ + BSZ) * 4;
    auto kfn = mma_gemm_kernel<BM, BN, TB, MODE, SPLITK>;
    cudaFuncSetAttribute(kfn, cudaFuncAttributeMaxDynamicSharedMemorySize, smem);
    kfn<<<grid, 128, smem, st>>>(A, B, C, N, K, ldA, ldB, sA, sB, sC,
                                 alpha, resid, rs, rsPtr, bias);
}

template<int MODE>
static void gemm(const float* A, const float* B, float* C,
                 int M, int N, int K, int batch, int ldA, int ldB,
                 long long sA, long long sB, long long sC, bool tb,
                 float alpha = 1.f,
                 const float* resid = nullptr, float rs = 0.f,
                 const float* rsPtr = nullptr,
                 const float* bias = nullptr,
                 bool forceBN64 = false,
                 cudaStream_t st = 0)
{
    if (N % 128 == 0 && !forceBN64) {
        dim3 grid(N / 128, M / 128, batch);
        if (tb)
            launch_gemm<128, 128, true , MODE, false>(grid, A, B, C, N, K,
                ldA, ldB, sA, sB, sC, alpha, resid, rs, rsPtr, bias, st);
        else
            launch_gemm<128, 128, false, MODE, false>(grid, A, B, C, N, K,
                ldA, ldB, sA, sB, sC, alpha, resid, rs, rsPtr, bias, st);
    } else {
        dim3 grid(N / 64, M / 128, batch);
        if (tb)
            launch_gemm<128, 64, true , MODE, false>(grid, A, B, C, N, K,
                ldA, ldB, sA, sB, sC, alpha, resid, rs, rsPtr, bias, st);
        else
            launch_gemm<128, 64, false, MODE, false>(grid, A, B, C, N, K,
                ldA, ldB, sA, sB, sC, alpha, resid, rs, rsPtr, bias, st);
    }
}

extern "C" void kernel_launch(void* const* d_in, const int* in_sizes, int n_in,
                              void* d_out, int out_size)
{
    const float* x      = (const float*)d_in[0];
    const float* ln_w   = (const float*)d_in[1];
    const float* ln_b   = (const float*)d_in[2];
    const float* w_qkv  = (const float*)d_in[3];
    const float* w_out  = (const float*)d_in[4];
    const float* b_out  = (const float*)d_in[5];
    const float* conv_w = (const float*)d_in[6];
    const float* omega  = (const float*)d_in[7];
    float* out = (float*)d_out;

    static cudaStream_t s2 = nullptr, s3 = nullptr;
    static cudaEvent_t evFork = nullptr, evInit = nullptr;
    static cudaEvent_t evJoinA = nullptr, evJoinB = nullptr;
    if (!s2) {
        cudaStreamCreateWithFlags(&s2, cudaStreamNonBlocking);
        cudaStreamCreateWithFlags(&s3, cudaStreamNonBlocking);
        cudaEventCreateWithFlags(&evFork,  cudaEventDisableTiming);
        cudaEventCreateWithFlags(&evInit,  cudaEventDisableTiming);
        cudaEventCreateWithFlags(&evJoinA, cudaEventDisableTiming);
        cudaEventCreateWithFlags(&evJoinB, cudaEventDisableTiming);
    }

    float* p_ln   = symaddr(g_ln);
    float* p_q    = symaddr(g_q);
    float* p_ql   = symaddr(g_ql);
    float* p_kl   = symaddr(g_kl);
    float* p_a1   = symaddr(g_a1);
    float* p_a2   = symaddr(g_a2);
    float* p_z0   = symaddr(g_z0);
    float* p_z1   = symaddr(g_z1);
    float* p_t1   = symaddr(g_t1);
    float* p_t2   = symaddr(g_t2);
    float* p_t3   = symaddr(g_t3);
    float* p_a3v  = symaddr(g_a3v);
    float* p_w    = symaddr(g_w);
    float* p_ctx  = symaddr(g_ctx);

    const long long sQ  = (long long)N_ * DH_;
    const long long sL  = (long long)M_ * DH_;
    const long long sS1 = (long long)N_ * M_;
    const long long sA2 = (long long)M_ * M_;

    // 1) layernorm (warp-per-row; also zeroes rsum/max scratch)
    ln_kernel<<<ROWS_ / 8, 256>>>(x, ln_w, ln_b);

    // 2) qkv projection, epilogue writes q (scaled), k, v head-major
    gemm<1>(p_ln, w_qkv, nullptr, ROWS_, 3 * DIM_, DIM_, 1, DIM_, 3 * DIM_,
            0, 0, 0, false);

    // 3) landmarks (feeds both branches)
    landmark_kernel<<<(2 * BH_ * M_ * DH_) / 256, 256>>>();

    // ---- fork: pinv shared init on s2 ----
    cudaEventRecord(evFork, 0);
    cudaStreamWaitEvent(s2, evFork, 0);

    sim_softmax_kernel<<<dim3(1, M_ / 64, BH_), 256, 0, s2>>>(
        p_ql, p_kl, p_a2, DH_, sL, sL, sA2);
    pinv_absmax_kernel<<<BH_, 256, 0, s2>>>();
    zinit_kernel<<<(BH_ * M_ * M_) / 256, 256, 0, s2>>>();
    cudaEventRecord(evInit, s2);
    cudaStreamWaitEvent(s3, evInit, 0);

    // ---- TWO parallel pinv chains (bh 0-15 on s2, 16-31 on s3) ----
    for (int half = 0; half < 2; half++) {
        cudaStream_t st = half ? s3 : s2;
        long long off = (long long)half * 16 * sA2;
        for (int it = 0; it < 6; it++) {
            float* zin  = ((it & 1) ? p_z1 : p_z0) + off;
            float* zout = ((it & 1) ? p_z0 : p_z1) + off;
            gemm<0>(p_a2 + off, zin, p_t1 + off, M_, M_, M_, 16, M_, M_,
                    sA2, sA2, sA2, false,
                    1.f, nullptr, 0.f, nullptr, nullptr, true, st);
            gemm<0>(p_t1 + off, p_t1 + off, p_t2 + off, M_, M_, M_, 16, M_, M_,
                    sA2, sA2, sA2, false,
                    -1.f, p_t1 + off, 7.f, nullptr, nullptr, true, st);
            gemm<0>(p_t1 + off, p_t2 + off, p_t3 + off, M_, M_, M_, 16, M_, M_,
                    sA2, sA2, sA2, false,
                    -1.f, p_t1 + off, 15.f, nullptr, nullptr, true, st);
            gemm<0>(zin, p_t3 + off, zout, M_, M_, M_, 16, M_, M_,
                    sA2, sA2, sA2, false,
                    -0.25f, zin, 3.25f, nullptr, nullptr, true, st);
        }
    }
    cudaEventRecord(evJoinA, s2);
    cudaEventRecord(evJoinB, s3);

    // ---- branch B (main stream) = sim1, flash(sim3*v), reduce, conv ----
    sim_softmax_kernel<<<dim3(1, N_ / 64, BH_), 256>>>(
        p_q, p_kl, p_a1, DH_, sQ, sL, sS1);
    {
        cudaFuncSetAttribute(a3v_flash_kernel,
                             cudaFuncAttributeMaxDynamicSharedMemorySize, FL_SMEM);
        a3v_flash_kernel<<<dim3(2, 2, BH_), 256, FL_SMEM>>>();
        a3v_reduce_kernel<<<(BH_ * M_ * DH_) / 256, 256>>>();
    }
    conv_add_kernel<<<BH_ * (N_ / 128), 256>>>(conv_w);

    // ---- join: main stream waits for both pinv chains (z0 complete) ----
    cudaStreamWaitEvent(0, evJoinA, 0);
    cudaStreamWaitEvent(0, evJoinB, 0);

    // 8) w = a2inv @ a3v  (tiny: 256x64x256)
    gemm<0>(p_z0, p_a3v, p_w, M_, DH_, M_, BH_, M_, DH_, sA2, sL, sL, false);

    // 9) ctx += a1 @ w  (accumulates onto conv residual)
    gemm<2>(p_a1, p_w, nullptr, N_, DH_, M_, BH_, M_, DH_, sS1, sL, 0, false);

    // 10) output projection + bias + omega * x
    gemm<0>(p_ctx, w_out, out, ROWS_, DIM_, DIM_, 1, DIM_, DIM_, 0, 0, 0, false,
            1.f, x, 0.f, omega, b_out);
}

// round 17
// speedup vs baseline: 1.0283x; 1.0283x over previous
#include <cuda_runtime.h>
#include <cuda_bf16.h>
#include <cstdint>

// ---------------------------------------------------------------------------
// Nystrom attention transformer layer. TF32 mma GEMMs, 64x64 warp tiles,
// cp.async pipelines, conflict-free smem, fused epilogues.
// Two-stream graph: pinv chain (depth-3 Newton-Schulz) overlaps
// sim1/flash(sim3*v)/conv. a3=exp(sim3) never materialized.
// ---------------------------------------------------------------------------

#define B_    4
#define N_    4096
#define DIM_  512
#define H_    8
#define DH_   64
#define M_    256
#define L_    16
#define ROWS_ (B_ * N_)          // 16384
#define BH_   (B_ * H_)          // 32

// ---------------- scratch (device globals) ----------------------------------
__device__ float g_ln  [ROWS_ * DIM_];
__device__ float g_q   [BH_ * N_ * DH_];
__device__ float g_k   [BH_ * N_ * DH_];
__device__ float g_v   [BH_ * N_ * DH_];
__device__ float g_ql  [BH_ * M_ * DH_];
__device__ float g_kl  [BH_ * M_ * DH_];
__device__ float g_a1  [BH_ * N_ * M_];
__device__ float g_a2  [BH_ * M_ * M_];
__device__ float g_z0  [BH_ * M_ * M_];
__device__ float g_z1  [BH_ * M_ * M_];
__device__ float g_t1  [BH_ * M_ * M_];   // y
__device__ float g_t2  [BH_ * M_ * M_];   // G
__device__ float g_t3  [BH_ * M_ * M_];   // w1
__device__ float g_a3v [BH_ * M_ * DH_];
__device__ float g_w   [BH_ * M_ * DH_];
__device__ float g_part[BH_ * 4 * M_ * DH_];
__device__ float g_rsum[BH_ * M_];
__device__ float g_ctx [ROWS_ * DIM_];
__device__ float g_max [2];

// ---------------- reductions -------------------------------------------------
__device__ __forceinline__ float blockReduceMax(float v, float* sh) {
    int tid = threadIdx.x;
    sh[tid] = v; __syncthreads();
    for (int s = 128; s > 0; s >>= 1) {
        if (tid < s) sh[tid] = fmaxf(sh[tid], sh[tid + s]);
        __syncthreads();
    }
    float r = sh[0]; __syncthreads();
    return r;
}

// ---------------- layernorm: warp per row, single pass ------------------------
__global__ __launch_bounds__(256) void ln_kernel(
    const float* __restrict__ x, const float* __restrict__ w,
    const float* __restrict__ b)
{
    int tid = threadIdx.x;
    if (blockIdx.x < 32) {
        g_rsum[blockIdx.x * 256 + tid] = 0.f;
        if (blockIdx.x == 0 && tid < 2) g_max[tid] = 0.f;
    }

    long long row = (long long)blockIdx.x * 8 + (tid >> 5);
    int lane = tid & 31;
    const float* xr = x + row * DIM_;

    float4 v[4];
    float s = 0.f, s2 = 0.f;
    #pragma unroll
    for (int i = 0; i < 4; i++) {
        v[i] = *(const float4*)(xr + (i * 32 + lane) * 4);
        s  += v[i].x + v[i].y + v[i].z + v[i].w;
        s2 += v[i].x * v[i].x + v[i].y * v[i].y
            + v[i].z * v[i].z + v[i].w * v[i].w;
    }
    #pragma unroll
    for (int d = 16; d > 0; d >>= 1) {
        s  += __shfl_xor_sync(0xffffffffu, s, d);
        s2 += __shfl_xor_sync(0xffffffffu, s2, d);
    }
    float mu  = s * (1.0f / DIM_);
    float var = s2 * (1.0f / DIM_) - mu * mu;
    float inv = rsqrtf(var + 1e-5f);

    float* dst = g_ln + row * DIM_;
    #pragma unroll
    for (int i = 0; i < 4; i++) {
        int col = (i * 32 + lane) * 4;
        float4 wv = *(const float4*)(w + col);
        float4 bv = *(const float4*)(b + col);
        float4 o;
        o.x = (v[i].x - mu) * inv * wv.x + bv.x;
        o.y = (v[i].y - mu) * inv * wv.y + bv.y;
        o.z = (v[i].z - mu) * inv * wv.z + bv.z;
        o.w = (v[i].w - mu) * inv * wv.w + bv.w;
        *(float4*)(dst + col) = o;
    }
}

// ---------------- mma + cp.async helpers -------------------------------------
__device__ __forceinline__ void mma_tf32(
    float& c0, float& c1, float& c2, float& c3,
    uint32_t a0, uint32_t a1, uint32_t a2, uint32_t a3,
    uint32_t b0, uint32_t b1)
{
    asm volatile(
        "mma.sync.aligned.m16n8k8.row.col.f32.tf32.tf32.f32 "
        "{%0,%1,%2,%3}, {%4,%5,%6,%7}, {%8,%9}, {%0,%1,%2,%3};"
        : "+f"(c0), "+f"(c1), "+f"(c2), "+f"(c3)
        : "r"(a0), "r"(a1), "r"(a2), "r"(a3), "r"(b0), "r"(b1));
}
__device__ __forceinline__ void cpa16(void* dst, const void* src) {
    uint32_t d = (uint32_t)__cvta_generic_to_shared(dst);
    asm volatile("cp.async.cg.shared.global [%0], [%1], 16;" :: "r"(d), "l"(src));
}
#define CP_COMMIT() asm volatile("cp.async.commit_group;" ::: "memory")
#define CP_WAIT1()  asm volatile("cp.async.wait_group 1;" ::: "memory")
#define CP_WAIT0()  asm volatile("cp.async.wait_group 0;" ::: "memory")

#define BK2 16
#define RS  20      // [row][k] stride (words): frag banks 20g+tg = all 32 distinct

// ---------------- main mma GEMM: 128 threads, 2x2 warps, 64x64 warp tile -----
// BN=128: 3-stage single-sync pipeline. BN=64: 2-stage, 3 CTAs/SM.
// MODE 0: standard epilogue (alpha, bias, resid, resid2); MODE 1: qkv split;
// MODE 2: ctx accumulate.
template<int BM, int BN, bool TB, int MODE, bool SPLITK>
__global__ __launch_bounds__(128, (BN == 64) ? 3 : 2) void mma_gemm_kernel(
    const float* __restrict__ A, const float* __restrict__ B,
    float* __restrict__ C, int Ndim, int Kdim, int ldA, int ldB,
    long long sA, long long sB, long long sC,
    float alpha,
    const float* __restrict__ resid, float residScale,
    const float* __restrict__ residScalePtr,
    const float* __restrict__ bias,
    const float* __restrict__ resid2, float residScale2)
{
    constexpr int MT = 4;
    constexpr int NT = BN / 16;
    constexpr int RSB = BN + 8;
    constexpr int ASZ = BM * RS;
    constexpr int BSZ = TB ? BN * RS : BK2 * RSB;
    constexpr int STG = ASZ + BSZ;
    constexpr int STAGES = (BN == 64) ? 2 : 3;

    extern __shared__ __align__(16) float smp[];

    int bz = blockIdx.z;
    long long aOff, bOff, cOff;
    if (SPLITK) {
        int bz0 = bz >> 2, sp = bz & 3;
        aOff = (long long)bz0 * sA + (long long)sp * Kdim;
        bOff = (long long)bz0 * sB + (long long)sp * Kdim * ldB;
        cOff = (long long)bz * sC;
    } else {
        aOff = (long long)bz * sA;
        bOff = (long long)bz * sB;
        cOff = (long long)bz * sC;
    }
    const float* Ab = A + aOff;
    const float* Bb = B + bOff;
    float*       Cb = C + cOff;
    const float* Rb  = resid  ? resid  + cOff : nullptr;
    const float* Rb2 = resid2 ? resid2 + cOff : nullptr;

    int n0 = blockIdx.x * BN;
    int m0 = blockIdx.y * BM;
    int tid  = threadIdx.x;
    int wid  = tid >> 5;
    int lane = tid & 31;
    int wm = wid >> 1, wn = wid & 1;
    int tm0 = wm * 64, tn0 = wn * (BN / 2);
    int g  = lane >> 2;
    int tg = lane & 3;

    float acc[MT][NT][4];
    #pragma unroll
    for (int i = 0; i < MT; i++)
        #pragma unroll
        for (int j = 0; j < NT; j++)
            #pragma unroll
            for (int c = 0; c < 4; c++) acc[i][j][c] = 0.f;

    auto loadTile = [&](int t, int st) {
        int k0 = t * BK2;
        float* As = smp + st * STG;
        float* Bs = As + ASZ;
        #pragma unroll
        for (int c = 0; c < BM / 32; c++) {
            int id = c * 128 + tid;
            int m = id >> 2, kq = (id & 3) * 4;
            cpa16(&As[m * RS + kq],
                  Ab + (long long)(m0 + m) * ldA + k0 + kq);
        }
        if (TB) {
            #pragma unroll
            for (int c = 0; c < BN / 32; c++) {
                int id = c * 128 + tid;
                int n = id >> 2, kq = (id & 3) * 4;
                cpa16(&Bs[n * RS + kq],
                      Bb + (long long)(n0 + n) * ldB + k0 + kq);
            }
        } else {
            constexpr int CPR = BN / 4;
            #pragma unroll
            for (int c = 0; c < BN / 32; c++) {
                int id = c * 128 + tid;
                int k = id / CPR, nq = (id % CPR) * 4;
                cpa16(&Bs[k * RSB + nq],
                      Bb + (long long)(k0 + k) * ldB + n0 + nq);
            }
        }
    };

    auto computeStage = [&](int st) {
        const float* as = smp + st * STG;
        const float* bs = as + ASZ;
        #pragma unroll
        for (int kk = 0; kk < BK2; kk += 8) {
            int c0 = kk + tg, c1 = c0 + 4;
            uint32_t af[MT][4], bf[NT][2];
            #pragma unroll
            for (int i = 0; i < MT; i++) {
                int r0 = (tm0 + i * 16 + g) * RS;
                int r1 = r0 + 8 * RS;
                af[i][0] = __float_as_uint(as[r0 + c0]);
                af[i][1] = __float_as_uint(as[r1 + c0]);
                af[i][2] = __float_as_uint(as[r0 + c1]);
                af[i][3] = __float_as_uint(as[r1 + c1]);
            }
            #pragma unroll
            for (int j = 0; j < NT; j++) {
                if (TB) {
                    int rn = (tn0 + j * 8 + g) * RS;
                    bf[j][0] = __float_as_uint(bs[rn + c0]);
                    bf[j][1] = __float_as_uint(bs[rn + c1]);
                } else {
                    int b0 = c0 * RSB + tn0 + j * 8 + g;
                    bf[j][0] = __float_as_uint(bs[b0]);
                    bf[j][1] = __float_as_uint(bs[b0 + 4 * RSB]);
                }
            }
            #pragma unroll
            for (int i = 0; i < MT; i++)
                #pragma unroll
                for (int j = 0; j < NT; j++)
                    mma_tf32(acc[i][j][0], acc[i][j][1], acc[i][j][2], acc[i][j][3],
                             af[i][0], af[i][1], af[i][2], af[i][3],
                             bf[j][0], bf[j][1]);
        }
    };

    int nIter = Kdim / BK2;
    loadTile(0, 0); CP_COMMIT();
    loadTile(1, 1); CP_COMMIT();
    int p = 0;
    if (STAGES == 3) {
        for (int t = 0; t < nIter; t++) {
            CP_WAIT1();
            __syncthreads();
            if (t + 2 < nIter) {
                int st = p + 2; if (st >= 3) st -= 3;
                loadTile(t + 2, st);
            }
            CP_COMMIT();
            computeStage(p);
            p = (p + 1 == 3) ? 0 : p + 1;
        }
    } else {
        for (int t = 0; t < nIter; t++) {
            CP_WAIT1();
            __syncthreads();
            computeStage(p);
            __syncthreads();
            if (t + 2 < nIter) loadTile(t + 2, p);
            CP_COMMIT();
            p ^= 1;
        }
    }

    float rs = residScalePtr ? *residScalePtr : residScale;
    #pragma unroll
    for (int i = 0; i < MT; i++) {
        int r0 = m0 + tm0 + i * 16 + g;
        int r1 = r0 + 8;
        #pragma unroll
        for (int j = 0; j < NT; j++) {
            int cc = n0 + tn0 + j * 8 + tg * 2;
            if (MODE == 0) {
                float2 bv = bias ? *(const float2*)(bias + cc) : make_float2(0.f, 0.f);
                float2 v0 = make_float2(alpha * acc[i][j][0] + bv.x,
                                        alpha * acc[i][j][1] + bv.y);
                float2 v1 = make_float2(alpha * acc[i][j][2] + bv.x,
                                        alpha * acc[i][j][3] + bv.y);
                if (Rb) {
                    float2 q0 = *(const float2*)(Rb + (long long)r0 * Ndim + cc);
                    float2 q1 = *(const float2*)(Rb + (long long)r1 * Ndim + cc);
                    v0.x += rs * q0.x; v0.y += rs * q0.y;
                    v1.x += rs * q1.x; v1.y += rs * q1.y;
                }
                if (Rb2) {
                    float2 q0 = *(const float2*)(Rb2 + (long long)r0 * Ndim + cc);
                    float2 q1 = *(const float2*)(Rb2 + (long long)r1 * Ndim + cc);
                    v0.x += residScale2 * q0.x; v0.y += residScale2 * q0.y;
                    v1.x += residScale2 * q1.x; v1.y += residScale2 * q1.y;
                }
                *(float2*)(Cb + (long long)r0 * Ndim + cc) = v0;
                *(float2*)(Cb + (long long)r1 * Ndim + cc) = v1;
            } else if (MODE == 1) {
                int which = cc >> 9;
                int hc = cc & 511;
                int h = hc >> 6, d = hc & 63;
                float sc = (which == 0) ? 0.125f : 1.0f;
                float* dstbuf = (which == 0) ? g_q : (which == 1) ? g_k : g_v;
                #pragma unroll
                for (int rr = 0; rr < 2; rr++) {
                    int row = rr ? r1 : r0;
                    int b = row >> 12, nn = row & 4095;
                    long long dst = (((long long)((b << 3) + h)) * N_ + nn) * DH_ + d;
                    float2 v = rr ? make_float2(sc * acc[i][j][2], sc * acc[i][j][3])
                                  : make_float2(sc * acc[i][j][0], sc * acc[i][j][1]);
                    *(float2*)(dstbuf + dst) = v;
                }
            } else {
                int b = bz >> 3, h = bz & 7;
                float* c0p = g_ctx + ((long long)(b * N_ + r0)) * DIM_ + h * DH_ + cc;
                float* c1p = g_ctx + ((long long)(b * N_ + r1)) * DIM_ + h * DH_ + cc;
                float2 o0 = *(float2*)c0p;
                float2 o1 = *(float2*)c1p;
                *(float2*)c0p = make_float2(o0.x + acc[i][j][0], o0.y + acc[i][j][1]);
                *(float2*)c1p = make_float2(o1.x + acc[i][j][2], o1.y + acc[i][j][3]);
            }
        }
    }
}

// ---------------- flash sim3*v (unchanged from R15) ---------------------------
#define FL_QL 0
#define FL_KS 8704
#define FL_VS 17408
#define FL_SS 26624
#define FL_SMEM ((26624 + 8704) * 4)  // 141312 B

__global__ __launch_bounds__(256, 1) void a3v_flash_kernel()
{
    extern __shared__ __align__(16) float fsm[];
    float* QL  = fsm + FL_QL;
    float* KS0 = fsm + FL_KS;
    float* VS0 = fsm + FL_VS;
    float* SS  = fsm + FL_SS;

    int ns = blockIdx.x;
    int mb = blockIdx.y;
    int bh = blockIdx.z;
    int m0 = mb * 128;
    const float* qlb = g_ql + (long long)bh * (M_ * DH_);
    const float* kb  = g_k + (long long)bh * (N_ * DH_) + (long long)ns * 2048 * DH_;
    const float* vb  = g_v + (long long)bh * (N_ * DH_) + (long long)ns * 2048 * DH_;

    int tid = threadIdx.x;
    int wid = tid >> 5, lane = tid & 31;
    int wm = wid >> 1, wn = wid & 1;
    int tm0 = wm * 32, tn0 = wn * 32;
    int g = lane >> 2, tg = lane & 3;

    auto loadKV = [&](int t, int st) {
        const float* kb2 = kb + (long long)t * 64 * DH_;
        const float* vb2 = vb + (long long)t * 64 * DH_;
        float* KS = KS0 + st * 4352;
        float* VS = VS0 + st * 4608;
        #pragma unroll
        for (int c = 0; c < 4; c++) {
            int id = c * 256 + tid;
            int n = id >> 4, kq = (id & 15) * 4;
            cpa16(&KS[n * 68 + kq], kb2 + (long long)n * DH_ + kq);
        }
        #pragma unroll
        for (int c = 0; c < 4; c++) {
            int id = c * 256 + tid;
            int k = id >> 4, nq = (id & 15) * 4;
            cpa16(&VS[k * 72 + nq], vb2 + (long long)k * DH_ + nq);
        }
    };

    #pragma unroll
    for (int c = 0; c < 8; c++) {
        int id = c * 256 + tid;
        int m = id >> 4, kq = (id & 15) * 4;
        cpa16(&QL[m * 68 + kq], qlb + (long long)(m0 + m) * DH_ + kq);
    }
    loadKV(0, 0);
    CP_COMMIT();

    float acc_o[2][4][4];
    #pragma unroll
    for (int i = 0; i < 2; i++)
        #pragma unroll
        for (int j = 0; j < 4; j++)
            #pragma unroll
            for (int c = 0; c < 4; c++) acc_o[i][j][c] = 0.f;
    float rsp[2][2] = {{0.f, 0.f}, {0.f, 0.f}};

    int p = 0;
    for (int t = 0; t < 32; t++) {
        if (t + 1 < 32) loadKV(t + 1, 1 - p);
        CP_COMMIT();
        CP_WAIT1();
        __syncthreads();

        const float* KS = KS0 + p * 4352;
        const float* VS = VS0 + p * 4608;

        float acc_s[2][4][4];
        #pragma unroll
        for (int i = 0; i < 2; i++)
            #pragma unroll
            for (int j = 0; j < 4; j++)
                #pragma unroll
                for (int c = 0; c < 4; c++) acc_s[i][j][c] = 0.f;

        #pragma unroll
        for (int kk = 0; kk < 64; kk += 8) {
            int c0 = kk + tg, c1 = c0 + 4;
            uint32_t af[2][4], bf[4][2];
            #pragma unroll
            for (int i = 0; i < 2; i++) {
                int r0 = (tm0 + i * 16 + g) * 68;
                int r1 = r0 + 8 * 68;
                af[i][0] = __float_as_uint(QL[r0 + c0]);
                af[i][1] = __float_as_uint(QL[r1 + c0]);
                af[i][2] = __float_as_uint(QL[r0 + c1]);
                af[i][3] = __float_as_uint(QL[r1 + c1]);
            }
            #pragma unroll
            for (int j = 0; j < 4; j++) {
                int rn = (tn0 + j * 8 + g) * 68;
                bf[j][0] = __float_as_uint(KS[rn + c0]);
                bf[j][1] = __float_as_uint(KS[rn + c1]);
            }
            #pragma unroll
            for (int i = 0; i < 2; i++)
                #pragma unroll
                for (int j = 0; j < 4; j++)
                    mma_tf32(acc_s[i][j][0], acc_s[i][j][1], acc_s[i][j][2], acc_s[i][j][3],
                             af[i][0], af[i][1], af[i][2], af[i][3],
                             bf[j][0], bf[j][1]);
        }

        #pragma unroll
        for (int i = 0; i < 2; i++) {
            int r0 = tm0 + i * 16 + g;
            int r1 = r0 + 8;
            #pragma unroll
            for (int j = 0; j < 4; j++) {
                int col = tn0 + j * 8 + tg * 2;
                float e0 = __expf(acc_s[i][j][0]);
                float e1 = __expf(acc_s[i][j][1]);
                float e2 = __expf(acc_s[i][j][2]);
                float e3 = __expf(acc_s[i][j][3]);
                rsp[i][0] += e0 + e1;
                rsp[i][1] += e2 + e3;
                *(float2*)(SS + r0 * 68 + col) = make_float2(e0, e1);
                *(float2*)(SS + r1 * 68 + col) = make_float2(e2, e3);
            }
        }
        __syncthreads();

        #pragma unroll
        for (int kk = 0; kk < 64; kk += 8) {
            int c0 = kk + tg, c1 = c0 + 4;
            uint32_t af[2][4], bf[4][2];
            #pragma unroll
            for (int i = 0; i < 2; i++) {
                int r0 = (tm0 + i * 16 + g) * 68;
                int r1 = r0 + 8 * 68;
                af[i][0] = __float_as_uint(SS[r0 + c0]);
                af[i][1] = __float_as_uint(SS[r1 + c0]);
                af[i][2] = __float_as_uint(SS[r0 + c1]);
                af[i][3] = __float_as_uint(SS[r1 + c1]);
            }
            #pragma unroll
            for (int j = 0; j < 4; j++) {
                int b0 = c0 * 72 + tn0 + j * 8 + g;
                bf[j][0] = __float_as_uint(VS[b0]);
                bf[j][1] = __float_as_uint(VS[b0 + 4 * 72]);
            }
            #pragma unroll
            for (int i = 0; i < 2; i++)
                #pragma unroll
                for (int j = 0; j < 4; j++)
                    mma_tf32(acc_o[i][j][0], acc_o[i][j][1], acc_o[i][j][2], acc_o[i][j][3],
                             af[i][0], af[i][1], af[i][2], af[i][3],
                             bf[j][0], bf[j][1]);
        }
        __syncthreads();
        p ^= 1;
    }

    long long pbase = ((long long)bh * 4 + ns) * (M_ * DH_);
    #pragma unroll
    for (int i = 0; i < 2; i++) {
        int r0 = tm0 + i * 16 + g;
        int r1 = r0 + 8;
        #pragma unroll
        for (int j = 0; j < 4; j++) {
            int col = tn0 + j * 8 + tg * 2;
            *(float2*)(g_part + pbase + (long long)(m0 + r0) * DH_ + col) =
                make_float2(acc_o[i][j][0], acc_o[i][j][1]);
            *(float2*)(g_part + pbase + (long long)(m0 + r1) * DH_ + col) =
                make_float2(acc_o[i][j][2], acc_o[i][j][3]);
        }
        float s0 = rsp[i][0], s1 = rsp[i][1];
        s0 += __shfl_xor_sync(0xffffffffu, s0, 1);
        s0 += __shfl_xor_sync(0xffffffffu, s0, 2);
        s1 += __shfl_xor_sync(0xffffffffu, s1, 1);
        s1 += __shfl_xor_sync(0xffffffffu, s1, 2);
        if (tg == 0) {
            atomicAdd(&g_rsum[bh * M_ + m0 + r0], s0);
            atomicAdd(&g_rsum[bh * M_ + m0 + r1], s1);
        }
    }
}

// ---------------- sim GEMM (TB) with fused full-row softmax ------------------
__global__ __launch_bounds__(256) void sim_softmax_kernel(
    const float* __restrict__ A, const float* __restrict__ Bm,
    float* __restrict__ C, int Kdim,
    long long sA, long long sB, long long sC)
{
    constexpr int BMs = 64;
    __shared__ __align__(16) float As[BMs * RS];
    __shared__ __align__(16) float Bs[256 * RS];
    __shared__ float redM[4][BMs];
    __shared__ float redS[4][BMs];

    int bz = blockIdx.z;
    const float* Ab = A + (long long)bz * sA;
    const float* Bb = Bm + (long long)bz * sB;
    float*       Cb = C + (long long)bz * sC;

    int m0 = blockIdx.y * BMs;
    int tid  = threadIdx.x;
    int wid  = tid >> 5;
    int lane = tid & 31;
    int wm = wid >> 2, wn = wid & 3;
    int tm0 = wm * 32, tn0 = wn * 64;
    int g  = lane >> 2;
    int tg = lane & 3;

    float acc[2][8][4];
    #pragma unroll
    for (int i = 0; i < 2; i++)
        #pragma unroll
        for (int j = 0; j < 8; j++)
            #pragma unroll
            for (int c = 0; c < 4; c++) acc[i][j][c] = 0.f;

    for (int k0 = 0; k0 < Kdim; k0 += BK2) {
        {
            int m = tid >> 2, kq = (tid & 3) * 4;
            cpa16(&As[m * RS + kq], Ab + (long long)(m0 + m) * Kdim + k0 + kq);
        }
        #pragma unroll
        for (int c = 0; c < 4; c++) {
            int id = c * 256 + tid;
            int n = id >> 2, kq = (id & 3) * 4;
            cpa16(&Bs[n * RS + kq], Bb + (long long)n * Kdim + k0 + kq);
        }
        CP_COMMIT();
        CP_WAIT0();
        __syncthreads();

        #pragma unroll
        for (int kk = 0; kk < BK2; kk += 8) {
            int c0 = kk + tg, c1 = c0 + 4;
            uint32_t af[2][4], bf[8][2];
            #pragma unroll
            for (int i = 0; i < 2; i++) {
                int r0 = (tm0 + i * 16 + g) * RS;
                int r1 = r0 + 8 * RS;
                af[i][0] = __float_as_uint(As[r0 + c0]);
                af[i][1] = __float_as_uint(As[r1 + c0]);
                af[i][2] = __float_as_uint(As[r0 + c1]);
                af[i][3] = __float_as_uint(As[r1 + c1]);
            }
            #pragma unroll
            for (int j = 0; j < 8; j++) {
                int rn = (tn0 + j * 8 + g) * RS;
                bf[j][0] = __float_as_uint(Bs[rn + c0]);
                bf[j][1] = __float_as_uint(Bs[rn + c1]);
            }
            #pragma unroll
            for (int i = 0; i < 2; i++)
                #pragma unroll
                for (int j = 0; j < 8; j++)
                    mma_tf32(acc[i][j][0], acc[i][j][1], acc[i][j][2], acc[i][j][3],
                             af[i][0], af[i][1], af[i][2], af[i][3],
                             bf[j][0], bf[j][1]);
        }
        __syncthreads();
    }

    #pragma unroll
    for (int i = 0; i < 2; i++) {
        float mx0 = -1e30f, mx1 = -1e30f;
        #pragma unroll
        for (int j = 0; j < 8; j++) {
            mx0 = fmaxf(mx0, fmaxf(acc[i][j][0], acc[i][j][1]));
            mx1 = fmaxf(mx1, fmaxf(acc[i][j][2], acc[i][j][3]));
        }
        mx0 = fmaxf(mx0, __shfl_xor_sync(0xffffffffu, mx0, 1));
        mx0 = fmaxf(mx0, __shfl_xor_sync(0xffffffffu, mx0, 2));
        mx1 = fmaxf(mx1, __shfl_xor_sync(0xffffffffu, mx1, 1));
        mx1 = fmaxf(mx1, __shfl_xor_sync(0xffffffffu, mx1, 2));
        if (tg == 0) {
            redM[wn][tm0 + i * 16 + g]     = mx0;
            redM[wn][tm0 + i * 16 + g + 8] = mx1;
        }
    }
    __syncthreads();
    #pragma unroll
    for (int i = 0; i < 2; i++) {
        int rb0 = tm0 + i * 16 + g, rb1 = rb0 + 8;
        float mx0 = fmaxf(fmaxf(redM[0][rb0], redM[1][rb0]),
                          fmaxf(redM[2][rb0], redM[3][rb0]));
        float mx1 = fmaxf(fmaxf(redM[0][rb1], redM[1][rb1]),
                          fmaxf(redM[2][rb1], redM[3][rb1]));
        float s0 = 0.f, s1 = 0.f;
        #pragma unroll
        for (int j = 0; j < 8; j++) {
            float e0 = __expf(acc[i][j][0] - mx0);
            float e1 = __expf(acc[i][j][1] - mx0);
            float e2 = __expf(acc[i][j][2] - mx1);
            float e3 = __expf(acc[i][j][3] - mx1);
            acc[i][j][0] = e0; acc[i][j][1] = e1;
            acc[i][j][2] = e2; acc[i][j][3] = e3;
            s0 += e0 + e1; s1 += e2 + e3;
        }
        s0 += __shfl_xor_sync(0xffffffffu, s0, 1);
        s0 += __shfl_xor_sync(0xffffffffu, s0, 2);
        s1 += __shfl_xor_sync(0xffffffffu, s1, 1);
        s1 += __shfl_xor_sync(0xffffffffu, s1, 2);
        if (tg == 0) { redS[wn][rb0] = s0; redS[wn][rb1] = s1; }
    }
    __syncthreads();
    #pragma unroll
    for (int i = 0; i < 2; i++) {
        int rb0 = tm0 + i * 16 + g, rb1 = rb0 + 8;
        float i0 = 1.f / (redS[0][rb0] + redS[1][rb0] + redS[2][rb0] + redS[3][rb0]);
        float i1 = 1.f / (redS[0][rb1] + redS[1][rb1] + redS[2][rb1] + redS[3][rb1]);
        int r0 = m0 + rb0, r1 = m0 + rb1;
        #pragma unroll
        for (int j = 0; j < 8; j++) {
            int cc = tn0 + j * 8 + tg * 2;
            *(float2*)(Cb + (long long)r0 * 256 + cc) =
                make_float2(acc[i][j][0] * i0, acc[i][j][1] * i0);
            *(float2*)(Cb + (long long)r1 * 256 + cc) =
                make_float2(acc[i][j][2] * i1, acc[i][j][3] * i1);
        }
    }
}

// ---------------- landmark means ---------------------------------------------
__global__ __launch_bounds__(256) void landmark_kernel()
{
    int id = blockIdx.x * 256 + threadIdx.x;
    const int half = BH_ * M_ * DH_;
    bool isK = id >= half;
    int t = isK ? id - half : id;
    int d  = t & 63;
    int m  = (t >> 6) & 255;
    int bh = t >> 14;
    const float* src = (isK ? g_k : g_q) + ((long long)bh * N_ + m * L_) * DH_ + d;
    float s = 0.f;
    #pragma unroll
    for (int l = 0; l < L_; l++) s += src[l * DH_];
    (isK ? g_kl : g_ql)[t] = s * (1.0f / L_);
}

// ---------------- a3v 2-split reduce + row normalize -------------------------
__global__ __launch_bounds__(256) void a3v_reduce_kernel()
{
    int idx = blockIdx.x * 256 + threadIdx.x;
    int rrow = idx >> 6;
    int bh = idx >> 14;
    int inner = idx & 16383;
    long long base = (long long)bh * 4 * 16384 + inner;
    float s = g_part[base] + g_part[base + 16384];
    g_a3v[idx] = s / g_rsum[rrow];
}

// ---------------- pinv init ---------------------------------------------------
__global__ __launch_bounds__(256) void pinv_absmax_kernel()
{
    __shared__ float sh[256];
    const float* X = g_a2 + (long long)blockIdx.x * (M_ * M_);
    int tid = threadIdx.x;
    float cs = 0.f, rs = 0.f;
    for (int j = 0; j < M_; j++) cs += fabsf(X[tid * M_ + j]);
    for (int i = 0; i < M_; i++) rs += fabsf(X[i * M_ + tid]);
    float cm = blockReduceMax(cs, sh);
    float rm = blockReduceMax(rs, sh);
    if (tid == 0) {
        atomicMax(reinterpret_cast<int*>(&g_max[0]), __float_as_int(cm));
        atomicMax(reinterpret_cast<int*>(&g_max[1]), __float_as_int(rm));
    }
}

__global__ __launch_bounds__(256) void zinit_kernel()
{
    long long id = (long long)blockIdx.x * 256 + threadIdx.x;
    float inv = 1.0f / (g_max[0] * g_max[1]);
    long long bh = id >> 16;
    int rem = (int)(id & 65535);
    int row = rem >> 8, col = rem & 255;
    g_z0[id] = g_a2[bh * (M_ * M_) + (long long)col * M_ + row] * inv;
}

// ---------------- depthwise conv residual: WRITES ctx (step 9 accumulates) ----
__global__ __launch_bounds__(256) void conv_add_kernel(const float* __restrict__ cw)
{
    __shared__ __align__(16) float sv[160 * 64];

    int bid = blockIdx.x;
    int bh = bid >> 5;
    int tile = bid & 31;
    int n0 = tile * 128;
    int h = bh & 7, b = bh >> 3;
    int tid = threadIdx.x;
    const float* vb = g_v + ((long long)bh << 18);

    #pragma unroll
    for (int c = 0; c < 10; c++) {
        int e = (c * 256 + tid) * 4;
        int r = e >> 6, d = e & 63;
        int gr = n0 - 16 + r;
        float4 val = make_float4(0.f, 0.f, 0.f, 0.f);
        if ((unsigned)gr < (unsigned)N_)
            val = *(const float4*)(vb + (long long)gr * DH_ + d);
        *(float4*)(sv + r * 64 + d) = val;
    }
    __syncthreads();

    int d = tid & 63, rg = tid >> 6;
    float wr[33];
    #pragma unroll
    for (int k = 0; k < 33; k++) wr[k] = cw[h * 33 + k];

    #pragma unroll
    for (int half = 0; half < 2; half++) {
        int ob = rg * 32 + half * 16;
        float in[48];
        #pragma unroll
        for (int j = 0; j < 48; j++) in[j] = sv[(ob + j) * 64 + d];
        #pragma unroll
        for (int i = 0; i < 16; i++) {
            float acc = 0.f;
            #pragma unroll
            for (int k = 0; k < 33; k++) acc += wr[k] * in[i + k];
            int grow = n0 + ob + i;
            g_ctx[((long long)(b * N_ + grow)) * DIM_ + h * DH_ + d] = acc;
        }
    }
}

// ---------------- host helpers -------------------------------------------------
static float* symaddr(const void* sym) {
    void* p = nullptr;
    cudaGetSymbolAddress(&p, sym);
    return (float*)p;
}

template<int BM, int BN, bool TB, int MODE, bool SPLITK>
static void launch_gemm(dim3 grid,
                 const float* A, const float* B, float* C,
                 int N, int K, int ldA, int ldB,
                 long long sA, long long sB, long long sC,
                 float alpha, const float* resid, float rs,
                 const float* rsPtr, const float* bias,
                 cudaStream_t st = 0,
                 const float* resid2 = nullptr, float rs2 = 0.f)
{
    constexpr int RSB = BN + 8;
    constexpr int ASZ = BM * RS;
    constexpr int BSZ = TB ? BN * RS : BK2 * RSB;
    constexpr int STAGES = (BN == 64) ? 2 : 3;
    int smem = STAGES * (ASZ + BSZ) * 4;
    auto kfn = mma_gemm_kernel<BM, BN, TB, MODE, SPLITK>;
    cudaFuncSetAttribute(kfn, cudaFuncAttributeMaxDynamicSharedMemorySize, smem);
    kfn<<<grid, 128, smem, st>>>(A, B, C, N, K, ldA, ldB, sA, sB, sC,
                                 alpha, resid, rs, rsPtr, bias, resid2, rs2);
}

template<int MODE>
static void gemm(const float* A, const float* B, float* C,
                 int M, int N, int K, int batch, int ldA, int ldB,
                 long long sA, long long sB, long long sC, bool tb,
                 float alpha = 1.f,
                 const float* resid = nullptr, float rs = 0.f,
                 const float* rsPtr = nullptr,
                 const float* bias = nullptr,
                 bool forceBN64 = false,
                 cudaStream_t st = 0,
                 const float* resid2 = nullptr, float rs2 = 0.f)
{
    if (N % 128 == 0 && !forceBN64) {
        dim3 grid(N / 128, M / 128, batch);
        if (tb)
            launch_gemm<128, 128, true , MODE, false>(grid, A, B, C, N, K,
                ldA, ldB, sA, sB, sC, alpha, resid, rs, rsPtr, bias, st, resid2, rs2);
        else
            launch_gemm<128, 128, false, MODE, false>(grid, A, B, C, N, K,
                ldA, ldB, sA, sB, sC, alpha, resid, rs, rsPtr, bias, st, resid2, rs2);
    } else {
        dim3 grid(N / 64, M / 128, batch);
        if (tb)
            launch_gemm<128, 64, true , MODE, false>(grid, A, B, C, N, K,
                ldA, ldB, sA, sB, sC, alpha, resid, rs, rsPtr, bias, st, resid2, rs2);
        else
            launch_gemm<128, 64, false, MODE, false>(grid, A, B, C, N, K,
                ldA, ldB, sA, sB, sC, alpha, resid, rs, rsPtr, bias, st, resid2, rs2);
    }
}

extern "C" void kernel_launch(void* const* d_in, const int* in_sizes, int n_in,
                              void* d_out, int out_size)
{
    const float* x      = (const float*)d_in[0];
    const float* ln_w   = (const float*)d_in[1];
    const float* ln_b   = (const float*)d_in[2];
    const float* w_qkv  = (const float*)d_in[3];
    const float* w_out  = (const float*)d_in[4];
    const float* b_out  = (const float*)d_in[5];
    const float* conv_w = (const float*)d_in[6];
    const float* omega  = (const float*)d_in[7];
    float* out = (float*)d_out;

    static cudaStream_t s2 = nullptr, s3 = nullptr;
    static cudaEvent_t evFork = nullptr, evJoin = nullptr;
    static cudaEvent_t evY = nullptr, evW = nullptr;
    if (!s2) {
        cudaStreamCreateWithFlags(&s2, cudaStreamNonBlocking);
        cudaStreamCreateWithFlags(&s3, cudaStreamNonBlocking);
        cudaEventCreateWithFlags(&evFork, cudaEventDisableTiming);
        cudaEventCreateWithFlags(&evJoin, cudaEventDisableTiming);
        cudaEventCreateWithFlags(&evY,    cudaEventDisableTiming);
        cudaEventCreateWithFlags(&evW,    cudaEventDisableTiming);
    }

    float* p_ln   = symaddr(g_ln);
    float* p_q    = symaddr(g_q);
    float* p_ql   = symaddr(g_ql);
    float* p_kl   = symaddr(g_kl);
    float* p_a1   = symaddr(g_a1);
    float* p_a2   = symaddr(g_a2);
    float* p_z0   = symaddr(g_z0);
    float* p_z1   = symaddr(g_z1);
    float* p_t1   = symaddr(g_t1);
    float* p_t2   = symaddr(g_t2);
    float* p_t3   = symaddr(g_t3);
    float* p_a3v  = symaddr(g_a3v);
    float* p_w    = symaddr(g_w);
    float* p_ctx  = symaddr(g_ctx);

    const long long sQ  = (long long)N_ * DH_;
    const long long sL  = (long long)M_ * DH_;
    const long long sS1 = (long long)N_ * M_;
    const long long sA2 = (long long)M_ * M_;

    // 1) layernorm (warp-per-row; also zeroes rsum/max scratch)
    ln_kernel<<<ROWS_ / 8, 256>>>(x, ln_w, ln_b);

    // 2) qkv projection, epilogue writes q (scaled), k, v head-major
    gemm<1>(p_ln, w_qkv, nullptr, ROWS_, 3 * DIM_, DIM_, 1, DIM_, 3 * DIM_,
            0, 0, 0, false);

    // 3) landmarks (feeds both branches)
    landmark_kernel<<<(2 * BH_ * M_ * DH_) / 256, 256>>>();

    // ---- fork: branch A (s2/s3) = pinv chain, depth-3 Newton-Schulz ----
    cudaEventRecord(evFork, 0);
    cudaStreamWaitEvent(s2, evFork, 0);

    sim_softmax_kernel<<<dim3(1, M_ / 64, BH_), 256, 0, s2>>>(
        p_ql, p_kl, p_a2, DH_, sL, sL, sA2);
    pinv_absmax_kernel<<<BH_, 256, 0, s2>>>();
    zinit_kernel<<<(BH_ * M_ * M_) / 256, 256, 0, s2>>>();

    // z' = w1@G + 3.25 z - 3.75 w1, with y = a2@z, G = 1.75y - 0.25 y@y, w1 = z@y
    for (int it = 0; it < 6; it++) {
        float* zin  = (it & 1) ? p_z1 : p_z0;
        float* zout = (it & 1) ? p_z0 : p_z1;
        // level 1 (s2): y = a2 @ zin -> t1
        gemm<0>(p_a2, zin, p_t1, M_, M_, M_, BH_, M_, M_, sA2, sA2, sA2, false,
                1.f, nullptr, 0.f, nullptr, nullptr, true, s2);
        cudaEventRecord(evY, s2);
        cudaStreamWaitEvent(s3, evY, 0);
        // level 2a (s2): G = -0.25 y@y + 1.75 y -> t2
        gemm<0>(p_t1, p_t1, p_t2, M_, M_, M_, BH_, M_, M_, sA2, sA2, sA2, false,
                -0.25f, p_t1, 1.75f, nullptr, nullptr, true, s2);
        // level 2b (s3): w1 = zin @ y -> t3
        gemm<0>(zin, p_t1, p_t3, M_, M_, M_, BH_, M_, M_, sA2, sA2, sA2, false,
                1.f, nullptr, 0.f, nullptr, nullptr, true, s3);
        cudaEventRecord(evW, s3);
        cudaStreamWaitEvent(s2, evW, 0);
        // level 3 (s2): zout = w1@G + 3.25 zin - 3.75 w1
        gemm<0>(p_t3, p_t2, zout, M_, M_, M_, BH_, M_, M_, sA2, sA2, sA2, false,
                1.f, zin, 3.25f, nullptr, nullptr, true, s2,
                p_t3, -3.75f);
    }

    // ---- branch B (main stream) = sim1, flash(sim3*v), reduce, conv ----
    sim_softmax_kernel<<<dim3(1, N_ / 64, BH_), 256>>>(
        p_q, p_kl, p_a1, DH_, sQ, sL, sS1);
    {
        cudaFuncSetAttribute(a3v_flash_kernel,
                             cudaFuncAttributeMaxDynamicSharedMemorySize, FL_SMEM);
        a3v_flash_kernel<<<dim3(2, 2, BH_), 256, FL_SMEM>>>();
        a3v_reduce_kernel<<<(BH_ * M_ * DH_) / 256, 256>>>();
    }
    conv_add_kernel<<<BH_ * (N_ / 128), 256>>>(conv_w);

    // ---- join: main stream waits for pinv result (z0; s2's last op) ----
    cudaEventRecord(evJoin, s2);
    cudaStreamWaitEvent(0, evJoin, 0);

    // 8) w = a2inv @ a3v  (tiny: 256x64x256)
    gemm<0>(p_z0, p_a3v, p_w, M_, DH_, M_, BH_, M_, DH_, sA2, sL, sL, false);

    // 9) ctx += a1 @ w  (accumulates onto conv residual)
    gemm<2>(p_a1, p_w, nullptr, N_, DH_, M_, BH_, M_, DH_, sS1, sL, 0, false);

    // 10) output projection + bias + omega * x
    gemm<0>(p_ctx, w_out, out, ROWS_, DIM_, DIM_, 1, DIM_, DIM_, 0, 0, 0, false,
            1.f, x, 0.f, omega, b_out);
}